// round 6
// baseline (speedup 1.0000x reference)
#include <cuda_runtime.h>
#include <cuda_fp16.h>
#include <cstdint>

#define MM 8192
#define KK 4096
#define NN 4096

// GEMM tiling (fp16 mainloop)
#define BM 256
#define BN 128
#define BK 64             // K elems per stage (128 bytes of fp16)
#define NST 4
#define NCHUNK (KK / BK)  // 64
#define RS 144            // smem row stride bytes (128B data + 16B pad)

#define A_STG (BM * RS)           // 36864
#define B_STG (BN * RS)           // 18432
#define STG (A_STG + B_STG)       // 55296
#define SMEM_REQ (NST * STG)      // 221184

// Scratch (device globals — no allocation allowed)
__device__ __half g_qA[(size_t)MM * KK];   // [M][K] fp16 (integer values)
__device__ __half g_qBT[(size_t)NN * KK];  // [N][K] fp16 (B transposed)
__device__ float g_lsc[MM];
__device__ float g_rsc[NN];
__device__ float g_pmax[32 * NN];

// ---------------------------------------------------------------------------
// Kernel 1: per-row absmax + quantize of lhs -> fp16 integers
// ---------------------------------------------------------------------------
__global__ __launch_bounds__(256) void quant_lhs_kernel(const float* __restrict__ lhs) {
    int row = blockIdx.x;
    int t = threadIdx.x;
    const float4* src = (const float4*)(lhs + (size_t)row * KK);
    float4 v[4];
    float m = 0.0f;
#pragma unroll
    for (int i = 0; i < 4; i++) {
        v[i] = src[i * 256 + t];
        m = fmaxf(m, fmaxf(fmaxf(fabsf(v[i].x), fabsf(v[i].y)),
                           fmaxf(fabsf(v[i].z), fabsf(v[i].w))));
    }
#pragma unroll
    for (int o = 16; o > 0; o >>= 1) m = fmaxf(m, __shfl_xor_sync(0xffffffffu, m, o));
    __shared__ float red[8];
    if ((t & 31) == 0) red[t >> 5] = m;
    __syncthreads();
    m = red[0];
#pragma unroll
    for (int i = 1; i < 8; i++) m = fmaxf(m, red[i]);

    float scale = m / 127.0f;
    if (scale == 0.0f) scale = 1.0f;
    if (t == 0) g_lsc[row] = scale;

    __half2* qdst = (__half2*)(g_qA + (size_t)row * KK);
#pragma unroll
    for (int i = 0; i < 4; i++) {
        float r0 = fminf(fmaxf(rintf(v[i].x / scale), -127.0f), 127.0f);
        float r1 = fminf(fmaxf(rintf(v[i].y / scale), -127.0f), 127.0f);
        float r2 = fminf(fmaxf(rintf(v[i].z / scale), -127.0f), 127.0f);
        float r3 = fminf(fmaxf(rintf(v[i].w / scale), -127.0f), 127.0f);
        qdst[(i * 256 + t) * 2 + 0] = __floats2half2_rn(r0, r1);
        qdst[(i * 256 + t) * 2 + 1] = __floats2half2_rn(r2, r3);
    }
}

// ---------------------------------------------------------------------------
// Kernel 2a/2b: per-column absmax of rhs
// ---------------------------------------------------------------------------
__global__ __launch_bounds__(256) void rhs_pmax_kernel(const float* __restrict__ rhs) {
    int n = blockIdx.x * 256 + threadIdx.x;
    int k0 = blockIdx.y * 128;
    const float* p = rhs + (size_t)k0 * NN + n;
    float m = 0.0f;
#pragma unroll 8
    for (int k = 0; k < 128; k++) m = fmaxf(m, fabsf(p[(size_t)k * NN]));
    g_pmax[blockIdx.y * NN + n] = m;
}

__global__ __launch_bounds__(256) void rhs_scale_kernel() {
    int n = blockIdx.x * 256 + threadIdx.x;
    float m = 0.0f;
#pragma unroll
    for (int i = 0; i < 32; i++) m = fmaxf(m, g_pmax[i * NN + n]);
    float s = m / 127.0f;
    if (s == 0.0f) s = 1.0f;
    g_rsc[n] = s;
}

// ---------------------------------------------------------------------------
// Kernel 3: quantize rhs + transpose into [N][K] fp16
// ---------------------------------------------------------------------------
__global__ __launch_bounds__(256) void quant_rhs_kernel(const float* __restrict__ rhs) {
    __shared__ __half tile[64][68];
    int k0 = blockIdx.y * 64, n0 = blockIdx.x * 64;
    int t = threadIdx.x;
    int nl = t & 63;
    int kl0 = t >> 6;
    float s = g_rsc[n0 + nl];
#pragma unroll
    for (int i = 0; i < 16; i++) {
        int kl = kl0 + i * 4;
        float v = rhs[(size_t)(k0 + kl) * NN + n0 + nl];
        float r = fminf(fmaxf(rintf(v / s), -127.0f), 127.0f);
        tile[kl][nl] = __float2half_rn(r);
    }
    __syncthreads();
    int k4 = t & 15;
    int nl2 = t >> 4;
#pragma unroll
    for (int i = 0; i < 4; i++) {
        int nn = nl2 + i * 16;
        __half2 p0 = __halves2half2(tile[k4 * 4 + 0][nn], tile[k4 * 4 + 1][nn]);
        __half2 p1 = __halves2half2(tile[k4 * 4 + 2][nn], tile[k4 * 4 + 3][nn]);
        uint2 pk;
        pk.x = *(uint32_t*)&p0;
        pk.y = *(uint32_t*)&p1;
        *(uint2*)&g_qBT[(size_t)(n0 + nn) * KK + k0 + k4 * 4] = pk;
    }
}

// ---------------------------------------------------------------------------
// Kernel 4: pipelined fp16 GEMM with ldmatrix fragment loads
// Block 256x128, 8 warps (4m x 2n), warp tile 64x64, 4-stage cp.async.
// ---------------------------------------------------------------------------
__device__ __forceinline__ void mma_f16(float& c0, float& c1, float& c2, float& c3,
                                        uint32_t a0, uint32_t a1, uint32_t a2, uint32_t a3,
                                        uint32_t b0, uint32_t b1) {
    asm volatile(
        "mma.sync.aligned.m16n8k16.row.col.f32.f16.f16.f32 "
        "{%0,%1,%2,%3}, {%4,%5,%6,%7}, {%8,%9}, {%0,%1,%2,%3};\n"
        : "+f"(c0), "+f"(c1), "+f"(c2), "+f"(c3)
        : "r"(a0), "r"(a1), "r"(a2), "r"(a3), "r"(b0), "r"(b1));
}

__device__ __forceinline__ void ldsm4(uint32_t& r0, uint32_t& r1, uint32_t& r2, uint32_t& r3,
                                      uint32_t addr) {
    asm volatile("ldmatrix.sync.aligned.m8n8.x4.shared.b16 {%0,%1,%2,%3}, [%4];"
                 : "=r"(r0), "=r"(r1), "=r"(r2), "=r"(r3) : "r"(addr));
}

__device__ __forceinline__ void cp16(uint32_t smem, const void* g) {
    asm volatile("cp.async.cg.shared.global [%0], [%1], 16;" :: "r"(smem), "l"(g));
}

__global__ void __launch_bounds__(256, 1)
gemm_f16_kernel(float* __restrict__ out) {
    extern __shared__ signed char sm[];
    uint32_t smb = (uint32_t)__cvta_generic_to_shared(sm);

    int tid = threadIdx.x;
    int warp = tid >> 5, lane = tid & 31;
    int wm = (warp & 3) * 64;    // warp m offset (4 warps over 256)
    int wn = (warp >> 2) * 64;   // warp n offset (2 warps over 128)
    int bm = blockIdx.y * BM, bn = blockIdx.x * BN;
    int grp = lane >> 2, tq = lane & 3;

    // cp.async mapping: A 8 chunks/thread, B 4 chunks/thread (16B each)
    const __half* gA[8];
    uint32_t sA[8];
#pragma unroll
    for (int p = 0; p < 8; p++) {
        int i = p * 256 + tid;
        int r = i >> 3, s = i & 7;
        gA[p] = g_qA + (size_t)(bm + r) * KK + s * 8;
        sA[p] = smb + r * RS + s * 16;
    }
    const __half* gB[4];
    uint32_t sB[4];
#pragma unroll
    for (int p = 0; p < 4; p++) {
        int i = p * 256 + tid;
        int r = i >> 3, s = i & 7;
        gB[p] = g_qBT + (size_t)(bn + r) * KK + s * 8;
        sB[p] = smb + A_STG + r * RS + s * 16;
    }

    // ldmatrix per-lane base addresses
    uint32_t aLd = smb + (wm + (lane & 15)) * RS + (lane >> 4) * 16;
    uint32_t bLd = smb + A_STG +
                   (wn + ((lane >> 4) & 1) * 8 + (lane & 7)) * RS + ((lane >> 3) & 1) * 16;

    float acc[4][8][4];
#pragma unroll
    for (int mi = 0; mi < 4; mi++)
#pragma unroll
        for (int ni = 0; ni < 8; ni++)
#pragma unroll
            for (int r = 0; r < 4; r++) acc[mi][ni][r] = 0.0f;

    // Prologue: stages 0..NST-2
#pragma unroll
    for (int st = 0; st < NST - 1; st++) {
#pragma unroll
        for (int p = 0; p < 8; p++) cp16(sA[p] + st * STG, gA[p] + st * BK);
#pragma unroll
        for (int p = 0; p < 4; p++) cp16(sB[p] + st * STG, gB[p] + st * BK);
        asm volatile("cp.async.commit_group;");
    }

    int stage = 0;
    for (int kt = 0; kt < NCHUNK; kt++) {
        asm volatile("cp.async.wait_group %0;" :: "n"(NST - 2));
        __syncthreads();

        if (kt + NST - 1 < NCHUNK) {
            int st = stage + (NST - 1) >= NST ? stage - 1 : stage + NST - 1;
            int ko = (kt + NST - 1) * BK;
#pragma unroll
            for (int p = 0; p < 8; p++) cp16(sA[p] + st * STG, gA[p] + ko);
#pragma unroll
            for (int p = 0; p < 4; p++) cp16(sB[p] + st * STG, gB[p] + ko);
        }
        asm volatile("cp.async.commit_group;");

        uint32_t stoff = stage * STG;
#pragma unroll
        for (int ks = 0; ks < 4; ks++) {   // four K=16 steps per 64-elem chunk
            uint32_t a[4][4], b[8][2];
#pragma unroll
            for (int mi = 0; mi < 4; mi++)
                ldsm4(a[mi][0], a[mi][1], a[mi][2], a[mi][3],
                      aLd + stoff + mi * 16 * RS + ks * 32);
#pragma unroll
            for (int np = 0; np < 4; np++)
                ldsm4(b[2 * np][0], b[2 * np][1], b[2 * np + 1][0], b[2 * np + 1][1],
                      bLd + stoff + np * 16 * RS + ks * 32);
#pragma unroll
            for (int mi = 0; mi < 4; mi++)
#pragma unroll
                for (int ni = 0; ni < 8; ni++)
                    mma_f16(acc[mi][ni][0], acc[mi][ni][1], acc[mi][ni][2], acc[mi][ni][3],
                            a[mi][0], a[mi][1], a[mi][2], a[mi][3], b[ni][0], b[ni][1]);
        }
        stage = (stage + 1 == NST) ? 0 : stage + 1;
    }

    // Epilogue: dequant + store
#pragma unroll
    for (int mi = 0; mi < 4; mi++) {
        int gm0 = bm + wm + mi * 16 + grp;
        float s0 = g_lsc[gm0];
        float s1 = g_lsc[gm0 + 8];
#pragma unroll
        for (int ni = 0; ni < 8; ni++) {
            int gn = bn + wn + ni * 8 + tq * 2;
            float r0 = g_rsc[gn];
            float r1 = g_rsc[gn + 1];
            float2 o0, o1;
            o0.x = acc[mi][ni][0] * s0 * r0;
            o0.y = acc[mi][ni][1] * s0 * r1;
            o1.x = acc[mi][ni][2] * s1 * r0;
            o1.y = acc[mi][ni][3] * s1 * r1;
            *(float2*)(out + (size_t)gm0 * NN + gn) = o0;
            *(float2*)(out + (size_t)(gm0 + 8) * NN + gn) = o1;
        }
    }
}

// ---------------------------------------------------------------------------
extern "C" void kernel_launch(void* const* d_in, const int* in_sizes, int n_in,
                              void* d_out, int out_size) {
    const float* lhs = (const float*)d_in[0];
    const float* rhs = (const float*)d_in[1];
    if (n_in >= 2 && in_sizes[0] == KK * NN && in_sizes[1] == MM * KK) {
        const float* t = lhs; lhs = rhs; rhs = t;
    }
    float* out = (float*)d_out;

    cudaFuncSetAttribute(gemm_f16_kernel, cudaFuncAttributeMaxDynamicSharedMemorySize, SMEM_REQ);

    quant_lhs_kernel<<<MM, 256>>>(lhs);
    rhs_pmax_kernel<<<dim3(NN / 256, 32), 256>>>(rhs);
    rhs_scale_kernel<<<NN / 256, 256>>>();
    quant_rhs_kernel<<<dim3(NN / 64, KK / 64), 256>>>(rhs);
    gemm_f16_kernel<<<dim3(NN / BN, MM / BM), 256, SMEM_REQ>>>(out);
}

// round 7
// speedup vs baseline: 1.0703x; 1.0703x over previous
#include <cuda_runtime.h>
#include <cuda_fp16.h>
#include <cstdint>

#define MM 8192
#define KK 4096
#define NN 4096

// GEMM tiling (fp16 mainloop)
#define BM 128
#define BN 128
#define BK 64             // K elems per stage (128 bytes of fp16)
#define NST 3
#define NCHUNK (KK / BK)  // 64
#define RS 144            // smem row stride bytes (128B data + 16B pad)

#define A_STG (BM * RS)           // 18432
#define B_STG (BN * RS)           // 18432
#define STG (A_STG + B_STG)       // 36864
#define SMEM_REQ (NST * STG)      // 110592  -> 2 CTAs/SM

// Scratch (device globals — no allocation allowed)
__device__ __half g_qA[(size_t)MM * KK];   // [M][K] fp16 (integer values)
__device__ __half g_qBT[(size_t)NN * KK];  // [N][K] fp16 (B transposed)
__device__ float g_lsc[MM];
__device__ float g_rsc[NN];
__device__ float g_pmax[32 * NN];

// ---------------------------------------------------------------------------
// Kernel 1: per-row absmax + quantize of lhs -> fp16 integers
// ---------------------------------------------------------------------------
__global__ __launch_bounds__(256) void quant_lhs_kernel(const float* __restrict__ lhs) {
    int row = blockIdx.x;
    int t = threadIdx.x;
    const float4* src = (const float4*)(lhs + (size_t)row * KK);
    float4 v[4];
    float m = 0.0f;
#pragma unroll
    for (int i = 0; i < 4; i++) {
        v[i] = src[i * 256 + t];
        m = fmaxf(m, fmaxf(fmaxf(fabsf(v[i].x), fabsf(v[i].y)),
                           fmaxf(fabsf(v[i].z), fabsf(v[i].w))));
    }
#pragma unroll
    for (int o = 16; o > 0; o >>= 1) m = fmaxf(m, __shfl_xor_sync(0xffffffffu, m, o));
    __shared__ float red[8];
    if ((t & 31) == 0) red[t >> 5] = m;
    __syncthreads();
    m = red[0];
#pragma unroll
    for (int i = 1; i < 8; i++) m = fmaxf(m, red[i]);

    float scale = m / 127.0f;
    if (scale == 0.0f) scale = 1.0f;
    if (t == 0) g_lsc[row] = scale;

    __half2* qdst = (__half2*)(g_qA + (size_t)row * KK);
#pragma unroll
    for (int i = 0; i < 4; i++) {
        float r0 = fminf(fmaxf(rintf(v[i].x / scale), -127.0f), 127.0f);
        float r1 = fminf(fmaxf(rintf(v[i].y / scale), -127.0f), 127.0f);
        float r2 = fminf(fmaxf(rintf(v[i].z / scale), -127.0f), 127.0f);
        float r3 = fminf(fmaxf(rintf(v[i].w / scale), -127.0f), 127.0f);
        qdst[(i * 256 + t) * 2 + 0] = __floats2half2_rn(r0, r1);
        qdst[(i * 256 + t) * 2 + 1] = __floats2half2_rn(r2, r3);
    }
}

// ---------------------------------------------------------------------------
// Kernel 2a/2b: per-column absmax of rhs
// ---------------------------------------------------------------------------
__global__ __launch_bounds__(256) void rhs_pmax_kernel(const float* __restrict__ rhs) {
    int n = blockIdx.x * 256 + threadIdx.x;
    int k0 = blockIdx.y * 128;
    const float* p = rhs + (size_t)k0 * NN + n;
    float m = 0.0f;
#pragma unroll 8
    for (int k = 0; k < 128; k++) m = fmaxf(m, fabsf(p[(size_t)k * NN]));
    g_pmax[blockIdx.y * NN + n] = m;
}

__global__ __launch_bounds__(256) void rhs_scale_kernel() {
    int n = blockIdx.x * 256 + threadIdx.x;
    float m = 0.0f;
#pragma unroll
    for (int i = 0; i < 32; i++) m = fmaxf(m, g_pmax[i * NN + n]);
    float s = m / 127.0f;
    if (s == 0.0f) s = 1.0f;
    g_rsc[n] = s;
}

// ---------------------------------------------------------------------------
// Kernel 3: quantize rhs + transpose into [N][K] fp16
// ---------------------------------------------------------------------------
__global__ __launch_bounds__(256) void quant_rhs_kernel(const float* __restrict__ rhs) {
    __shared__ __half tile[64][68];
    int k0 = blockIdx.y * 64, n0 = blockIdx.x * 64;
    int t = threadIdx.x;
    int nl = t & 63;
    int kl0 = t >> 6;
    float s = g_rsc[n0 + nl];
#pragma unroll
    for (int i = 0; i < 16; i++) {
        int kl = kl0 + i * 4;
        float v = rhs[(size_t)(k0 + kl) * NN + n0 + nl];
        float r = fminf(fmaxf(rintf(v / s), -127.0f), 127.0f);
        tile[kl][nl] = __float2half_rn(r);
    }
    __syncthreads();
    int k4 = t & 15;
    int nl2 = t >> 4;
#pragma unroll
    for (int i = 0; i < 4; i++) {
        int nn = nl2 + i * 16;
        __half2 p0 = __halves2half2(tile[k4 * 4 + 0][nn], tile[k4 * 4 + 1][nn]);
        __half2 p1 = __halves2half2(tile[k4 * 4 + 2][nn], tile[k4 * 4 + 3][nn]);
        uint2 pk;
        pk.x = *(uint32_t*)&p0;
        pk.y = *(uint32_t*)&p1;
        *(uint2*)&g_qBT[(size_t)(n0 + nn) * KK + k0 + k4 * 4] = pk;
    }
}

// ---------------------------------------------------------------------------
// Kernel 4: pipelined fp16 GEMM with ldmatrix fragment loads
// Block 128x128, 8 warps (2m x 4n), warp tile 64x32, 3-stage cp.async,
// 2 CTAs/SM (barrier bubbles of one CTA hidden by the other).
// ---------------------------------------------------------------------------
__device__ __forceinline__ void mma_f16(float& c0, float& c1, float& c2, float& c3,
                                        uint32_t a0, uint32_t a1, uint32_t a2, uint32_t a3,
                                        uint32_t b0, uint32_t b1) {
    asm volatile(
        "mma.sync.aligned.m16n8k16.row.col.f32.f16.f16.f32 "
        "{%0,%1,%2,%3}, {%4,%5,%6,%7}, {%8,%9}, {%0,%1,%2,%3};\n"
        : "+f"(c0), "+f"(c1), "+f"(c2), "+f"(c3)
        : "r"(a0), "r"(a1), "r"(a2), "r"(a3), "r"(b0), "r"(b1));
}

__device__ __forceinline__ void ldsm4(uint32_t& r0, uint32_t& r1, uint32_t& r2, uint32_t& r3,
                                      uint32_t addr) {
    asm volatile("ldmatrix.sync.aligned.m8n8.x4.shared.b16 {%0,%1,%2,%3}, [%4];"
                 : "=r"(r0), "=r"(r1), "=r"(r2), "=r"(r3) : "r"(addr));
}

__device__ __forceinline__ void cp16(uint32_t smem, const void* g) {
    asm volatile("cp.async.cg.shared.global [%0], [%1], 16;" :: "r"(smem), "l"(g));
}

__global__ void __launch_bounds__(256, 2)
gemm_f16_kernel(float* __restrict__ out) {
    extern __shared__ signed char sm[];
    uint32_t smb = (uint32_t)__cvta_generic_to_shared(sm);

    int tid = threadIdx.x;
    int warp = tid >> 5, lane = tid & 31;
    int wm = (warp & 1) * 64;    // warp m offset (2 warps over 128)
    int wn = (warp >> 1) * 32;   // warp n offset (4 warps over 128)
    int bm = blockIdx.y * BM, bn = blockIdx.x * BN;
    int grp = lane >> 2, tq = lane & 3;

    // cp.async mapping: A 4 chunks/thread, B 4 chunks/thread (16B each)
    const __half* gA[4];
    uint32_t sA[4];
#pragma unroll
    for (int p = 0; p < 4; p++) {
        int i = p * 256 + tid;
        int r = i >> 3, s = i & 7;
        gA[p] = g_qA + (size_t)(bm + r) * KK + s * 8;
        sA[p] = smb + r * RS + s * 16;
    }
    const __half* gB[4];
    uint32_t sB[4];
#pragma unroll
    for (int p = 0; p < 4; p++) {
        int i = p * 256 + tid;
        int r = i >> 3, s = i & 7;
        gB[p] = g_qBT + (size_t)(bn + r) * KK + s * 8;
        sB[p] = smb + A_STG + r * RS + s * 16;
    }

    // ldmatrix per-lane base addresses
    uint32_t aLd = smb + (wm + (lane & 15)) * RS + (lane >> 4) * 16;
    uint32_t bLd = smb + A_STG +
                   (wn + ((lane >> 4) & 1) * 8 + (lane & 7)) * RS + ((lane >> 3) & 1) * 16;

    float acc[4][4][4];
#pragma unroll
    for (int mi = 0; mi < 4; mi++)
#pragma unroll
        for (int ni = 0; ni < 4; ni++)
#pragma unroll
            for (int r = 0; r < 4; r++) acc[mi][ni][r] = 0.0f;

    // Prologue: stages 0..NST-2
#pragma unroll
    for (int st = 0; st < NST - 1; st++) {
#pragma unroll
        for (int p = 0; p < 4; p++) cp16(sA[p] + st * STG, gA[p] + st * BK);
#pragma unroll
        for (int p = 0; p < 4; p++) cp16(sB[p] + st * STG, gB[p] + st * BK);
        asm volatile("cp.async.commit_group;");
    }

    int stage = 0;
    for (int kt = 0; kt < NCHUNK; kt++) {
        asm volatile("cp.async.wait_group %0;" :: "n"(NST - 2));
        __syncthreads();

        if (kt + NST - 1 < NCHUNK) {
            int st = stage + (NST - 1) >= NST ? stage - 1 : stage + NST - 1;
            int ko = (kt + NST - 1) * BK;
#pragma unroll
            for (int p = 0; p < 4; p++) cp16(sA[p] + st * STG, gA[p] + ko);
#pragma unroll
            for (int p = 0; p < 4; p++) cp16(sB[p] + st * STG, gB[p] + ko);
        }
        asm volatile("cp.async.commit_group;");

        uint32_t stoff = stage * STG;
#pragma unroll
        for (int ks = 0; ks < 4; ks++) {   // four K=16 steps per 64-elem chunk
            uint32_t a[4][4], b[4][2];
#pragma unroll
            for (int mi = 0; mi < 4; mi++)
                ldsm4(a[mi][0], a[mi][1], a[mi][2], a[mi][3],
                      aLd + stoff + mi * 16 * RS + ks * 32);
#pragma unroll
            for (int np = 0; np < 2; np++)
                ldsm4(b[2 * np][0], b[2 * np][1], b[2 * np + 1][0], b[2 * np + 1][1],
                      bLd + stoff + np * 16 * RS + ks * 32);
#pragma unroll
            for (int mi = 0; mi < 4; mi++)
#pragma unroll
                for (int ni = 0; ni < 4; ni++)
                    mma_f16(acc[mi][ni][0], acc[mi][ni][1], acc[mi][ni][2], acc[mi][ni][3],
                            a[mi][0], a[mi][1], a[mi][2], a[mi][3], b[ni][0], b[ni][1]);
        }
        stage = (stage + 1 == NST) ? 0 : stage + 1;
    }

    // Epilogue: dequant + store
#pragma unroll
    for (int mi = 0; mi < 4; mi++) {
        int gm0 = bm + wm + mi * 16 + grp;
        float s0 = g_lsc[gm0];
        float s1 = g_lsc[gm0 + 8];
#pragma unroll
        for (int ni = 0; ni < 4; ni++) {
            int gn = bn + wn + ni * 8 + tq * 2;
            float r0 = g_rsc[gn];
            float r1 = g_rsc[gn + 1];
            float2 o0, o1;
            o0.x = acc[mi][ni][0] * s0 * r0;
            o0.y = acc[mi][ni][1] * s0 * r1;
            o1.x = acc[mi][ni][2] * s1 * r0;
            o1.y = acc[mi][ni][3] * s1 * r1;
            *(float2*)(out + (size_t)gm0 * NN + gn) = o0;
            *(float2*)(out + (size_t)(gm0 + 8) * NN + gn) = o1;
        }
    }
}

// ---------------------------------------------------------------------------
extern "C" void kernel_launch(void* const* d_in, const int* in_sizes, int n_in,
                              void* d_out, int out_size) {
    const float* lhs = (const float*)d_in[0];
    const float* rhs = (const float*)d_in[1];
    if (n_in >= 2 && in_sizes[0] == KK * NN && in_sizes[1] == MM * KK) {
        const float* t = lhs; lhs = rhs; rhs = t;
    }
    float* out = (float*)d_out;

    cudaFuncSetAttribute(gemm_f16_kernel, cudaFuncAttributeMaxDynamicSharedMemorySize, SMEM_REQ);

    quant_lhs_kernel<<<MM, 256>>>(lhs);
    rhs_pmax_kernel<<<dim3(NN / 256, 32), 256>>>(rhs);
    rhs_scale_kernel<<<NN / 256, 256>>>();
    quant_rhs_kernel<<<dim3(NN / 64, KK / 64), 256>>>(rhs);
    gemm_f16_kernel<<<dim3(NN / BN, MM / BM), 256, SMEM_REQ>>>(out);
}